// round 1
// baseline (speedup 1.0000x reference)
#include <cuda_runtime.h>
#include <math.h>

// Problem constants
#define BATCH 4
#define SEQ   2048
#define EMBD  1024
#define NHEAD 16
#define HDIM  64          // EMBD / NHEAD
#define QKV_C (3 * EMBD)  // 3072

// Scratch (device globals — no allocation allowed)
__device__ float g_qkv[BATCH * SEQ * QKV_C];   // [B,S,3C]
__device__ float g_y[BATCH * SEQ * EMBD];      // [B,S,C] attention output (heads merged)

// ---------------------------------------------------------------------------
// SGEMM: C[M,N] = A[M,K] @ B[K,N] + bias[N]
// Block tile 128x128, K-tile 8, 256 threads, 8x8 per-thread tile.
// Requires M%128==0, N%128==0, K%8==0 (true for all our shapes).
// ---------------------------------------------------------------------------
__global__ __launch_bounds__(256, 2)
void sgemm_bias(const float* __restrict__ A, const float* __restrict__ B,
                const float* __restrict__ bias, float* __restrict__ C,
                int M, int N, int K) {
    const int BM = 128, BN = 128, BK = 8, TM = 8, TN = 8;
    __shared__ float As[BK][BM];
    __shared__ float Bs[BK][BN];

    const int tid = threadIdx.x;               // 0..255
    const int trow = tid / 16;                 // 0..15
    const int tcol = tid % 16;                 // 0..15
    const int rowBase = blockIdx.y * BM;
    const int colBase = blockIdx.x * BN;

    // Load mapping
    const int aRow = tid >> 1;                 // 0..127
    const int aCol = (tid & 1) * 4;            // 0 or 4
    const int bRow = tid >> 5;                 // 0..7
    const int bCol = (tid & 31) * 4;           // 0..124

    float acc[TM][TN];
    #pragma unroll
    for (int i = 0; i < TM; i++)
        #pragma unroll
        for (int j = 0; j < TN; j++) acc[i][j] = 0.0f;

    for (int k0 = 0; k0 < K; k0 += BK) {
        float4 a4 = *(const float4*)&A[(long)(rowBase + aRow) * K + k0 + aCol];
        As[aCol + 0][aRow] = a4.x;
        As[aCol + 1][aRow] = a4.y;
        As[aCol + 2][aRow] = a4.z;
        As[aCol + 3][aRow] = a4.w;
        float4 b4 = *(const float4*)&B[(long)(k0 + bRow) * N + colBase + bCol];
        *(float4*)&Bs[bRow][bCol] = b4;
        __syncthreads();

        #pragma unroll
        for (int kk = 0; kk < BK; kk++) {
            float ar[TM], br[TN];
            #pragma unroll
            for (int i = 0; i < TM; i++) ar[i] = As[kk][trow * TM + i];
            #pragma unroll
            for (int j = 0; j < TN; j++) br[j] = Bs[kk][tcol * TN + j];
            #pragma unroll
            for (int i = 0; i < TM; i++)
                #pragma unroll
                for (int j = 0; j < TN; j++)
                    acc[i][j] = fmaf(ar[i], br[j], acc[i][j]);
        }
        __syncthreads();
    }

    #pragma unroll
    for (int i = 0; i < TM; i++) {
        const long r = rowBase + trow * TM + i;
        #pragma unroll
        for (int j = 0; j < TN; j += 4) {
            const int c = colBase + tcol * TN + j;
            float4 o;
            o.x = acc[i][j + 0] + bias[c + 0];
            o.y = acc[i][j + 1] + bias[c + 1];
            o.z = acc[i][j + 2] + bias[c + 2];
            o.w = acc[i][j + 3] + bias[c + 3];
            *(float4*)&C[r * N + c] = o;
        }
    }
}

// ---------------------------------------------------------------------------
// Flash attention (fp32, causal). One CTA per (q-block of 64, head, batch).
// 64 threads: thread t owns query row qb*64 + t.
// q and accumulator in registers; K/V/S tiles in static smem (48 KB).
// ---------------------------------------------------------------------------
__global__ __launch_bounds__(64)
void flash_attn(const float* __restrict__ qkv, float* __restrict__ y) {
    const int BQ = 64, BK = 64, NE = HDIM;
    const int qb = blockIdx.x;      // 0..31
    const int h  = blockIdx.y;      // 0..15
    const int b  = blockIdx.z;      // 0..3
    const int tid = threadIdx.x;    // 0..63
    const int qrow = qb * BQ + tid;
    const float scale = 0.125f;     // 1/sqrt(64)

    __shared__ float Ks[BK][NE];    // 16 KB
    __shared__ float Vs[BK][NE];    // 16 KB
    __shared__ float Ss[BK][BQ];    // 16 KB  (Ss[j][tid])

    // Load Q row into registers (pre-scaled)
    float q[NE];
    const float* qptr = qkv + ((long)b * SEQ + qrow) * QKV_C + h * NE;
    #pragma unroll
    for (int e = 0; e < NE; e += 4) {
        float4 v = *(const float4*)&qptr[e];
        q[e + 0] = v.x * scale;
        q[e + 1] = v.y * scale;
        q[e + 2] = v.z * scale;
        q[e + 3] = v.w * scale;
    }

    float acc[NE];
    #pragma unroll
    for (int e = 0; e < NE; e++) acc[e] = 0.0f;
    float m = -INFINITY, l = 0.0f;

    const int nkb = qb + 1;  // causal: only k-blocks <= q-block
    for (int kb = 0; kb < nkb; kb++) {
        // Cooperative K/V tile load: thread t loads row t of the tile.
        const float* kbase = qkv + ((long)b * SEQ + kb * BK + tid) * QKV_C + EMBD + h * NE;
        const float* vbase = kbase + EMBD;
        #pragma unroll
        for (int e = 0; e < NE; e += 4) {
            *(float4*)&Ks[tid][e] = *(const float4*)&kbase[e];
            *(float4*)&Vs[tid][e] = *(const float4*)&vbase[e];
        }
        __syncthreads();

        // Causal bound: within diagonal block, j <= tid.
        const int jmax = (kb == qb) ? (tid + 1) : BK;

        // Pass 1: scores + running max
        float newm = m;
        for (int j = 0; j < jmax; j++) {
            float s = 0.0f;
            #pragma unroll
            for (int e = 0; e < NE; e += 4) {
                float4 kv = *(const float4*)&Ks[j][e];
                s = fmaf(q[e + 0], kv.x, s);
                s = fmaf(q[e + 1], kv.y, s);
                s = fmaf(q[e + 2], kv.z, s);
                s = fmaf(q[e + 3], kv.w, s);
            }
            Ss[j][tid] = s;
            newm = fmaxf(newm, s);
        }

        // Pass 2: rescale + accumulate P@V
        const float corr = __expf(m - newm);
        l *= corr;
        #pragma unroll
        for (int e = 0; e < NE; e++) acc[e] *= corr;
        for (int j = 0; j < jmax; j++) {
            const float p = __expf(Ss[j][tid] - newm);
            l += p;
            #pragma unroll
            for (int e = 0; e < NE; e += 4) {
                float4 vv = *(const float4*)&Vs[j][e];
                acc[e + 0] = fmaf(p, vv.x, acc[e + 0]);
                acc[e + 1] = fmaf(p, vv.y, acc[e + 1]);
                acc[e + 2] = fmaf(p, vv.z, acc[e + 2]);
                acc[e + 3] = fmaf(p, vv.w, acc[e + 3]);
            }
        }
        m = newm;
        __syncthreads();
    }

    // Write merged-head output: y[b, qrow, h*64 + e]
    const float inv_l = 1.0f / l;
    float* optr = y + ((long)b * SEQ + qrow) * EMBD + h * NE;
    #pragma unroll
    for (int e = 0; e < NE; e += 4) {
        float4 o;
        o.x = acc[e + 0] * inv_l;
        o.y = acc[e + 1] * inv_l;
        o.z = acc[e + 2] * inv_l;
        o.w = acc[e + 3] * inv_l;
        *(float4*)&optr[e] = o;
    }
}

// ---------------------------------------------------------------------------
extern "C" void kernel_launch(void* const* d_in, const int* in_sizes, int n_in,
                              void* d_out, int out_size) {
    const float* x      = (const float*)d_in[0];  // [4,2048,1024]
    const float* W_attn = (const float*)d_in[1];  // [1024,3072]
    const float* b_attn = (const float*)d_in[2];  // [3072]
    const float* W_proj = (const float*)d_in[3];  // [1024,1024]
    const float* b_proj = (const float*)d_in[4];  // [1024]
    float* out = (float*)d_out;                   // [4,2048,1024]

    float* qkv;
    float* y;
    cudaGetSymbolAddress((void**)&qkv, g_qkv);
    cudaGetSymbolAddress((void**)&y, g_y);

    const int M = BATCH * SEQ;  // 8192

    // 1) QKV projection: [8192,1024] @ [1024,3072] + b_attn
    {
        dim3 grid(QKV_C / 128, M / 128);
        sgemm_bias<<<grid, 256>>>(x, W_attn, b_attn, qkv, M, QKV_C, EMBD);
    }

    // 2) Causal flash attention
    {
        dim3 grid(SEQ / 64, NHEAD, BATCH);
        flash_attn<<<grid, 64>>>(qkv, y);
    }

    // 3) Output projection: [8192,1024] @ [1024,1024] + b_proj
    {
        dim3 grid(EMBD / 128, M / 128);
        sgemm_bias<<<grid, 256>>>(y, W_proj, b_proj, out, M, EMBD, EMBD);
    }
}

// round 3
// speedup vs baseline: 1.4485x; 1.4485x over previous
#include <cuda_runtime.h>
#include <math.h>
#include <stdint.h>

// Problem constants
#define BATCH 4
#define SEQ   2048
#define EMBD  1024
#define NHEAD 16
#define HDIM  64
#define QKV_C (3 * EMBD)

// Scratch (device globals — no allocation allowed)
__device__ float g_qkv[BATCH * SEQ * QKV_C];
__device__ float g_y[BATCH * SEQ * EMBD];

// ---------------------------------------------------------------------------
// Helpers
// ---------------------------------------------------------------------------
__device__ __forceinline__ uint32_t smem_u32(const void* p) {
    uint32_t a;
    asm("{ .reg .u64 t; cvta.to.shared.u64 t, %1; cvt.u32.u64 %0, t; }" : "=r"(a) : "l"(p));
    return a;
}
__device__ __forceinline__ uint32_t f2tf32(float f) {
    uint32_t o;
    asm("cvt.rna.tf32.f32 %0, %1;" : "=r"(o) : "f"(f));
    return o;
}
#define CP_ASYNC16(dst_u32, src_ptr) \
    asm volatile("cp.async.cg.shared.global [%0], [%1], 16;" :: "r"(dst_u32), "l"(src_ptr))
#define CP_COMMIT() asm volatile("cp.async.commit_group;" ::: "memory")
#define CP_WAIT(n)  asm volatile("cp.async.wait_group %0;" :: "n"(n) : "memory")

__device__ __forceinline__ void mma_tf32(float& c0, float& c1, float& c2, float& c3,
                                         uint32_t a0, uint32_t a1, uint32_t a2, uint32_t a3,
                                         uint32_t b0, uint32_t b1) {
    asm volatile(
        "mma.sync.aligned.m16n8k8.row.col.f32.tf32.tf32.f32 "
        "{%0,%1,%2,%3}, {%4,%5,%6,%7}, {%8,%9}, {%0,%1,%2,%3};"
        : "+f"(c0), "+f"(c1), "+f"(c2), "+f"(c3)
        : "r"(a0), "r"(a1), "r"(a2), "r"(a3), "r"(b0), "r"(b1));
}

// ---------------------------------------------------------------------------
// TF32 mma.sync GEMM: C[M,N] = A[M,K] @ B[K,N] + bias[N]
// CTA tile 128x128, BK=32, 256 threads (8 warps: 2 M-rows x 4 N-cols),
// warp tile 64x32. Double-buffered cp.async pipeline.
//
// SMEM layouts (padded, conflict-free fragment loads):
//   A tile: [128 rows(M)][36 f32]   (32 K + 4 pad)  = 18432 B
//   B tile: [32 rows(K)][136 f32]   (128 N + 8 pad) = 17408 B
// ---------------------------------------------------------------------------
#define A_STRIDE 36
#define B_STRIDE 136
#define A_BYTES  (128 * A_STRIDE * 4)      // 18432
#define B_BYTES  (32 * B_STRIDE * 4)       // 17408
#define BUF_BYTES (A_BYTES + B_BYTES)      // 35840
#define SMEM_BYTES (2 * BUF_BYTES)         // 71680

__global__ __launch_bounds__(256)
void gemm_tf32(const float* __restrict__ A, const float* __restrict__ B,
               const float* __restrict__ bias, float* __restrict__ C,
               int M, int N, int K) {
    extern __shared__ char smem[];
    const int tid  = threadIdx.x;
    const int wid  = tid >> 5;
    const int lane = tid & 31;
    const int wm   = wid >> 2;        // 0..1
    const int wn   = wid & 3;         // 0..3
    const int grp  = lane >> 2;       // 0..7
    const int tig  = lane & 3;        // 0..3

    const long rowBase = (long)blockIdx.y * 128;
    const long colBase = (long)blockIdx.x * 128;
    const uint32_t sbase = smem_u32(smem);

    // cp.async load mapping
    const int aR  = tid >> 1;                 // 0..127  (2 float4 per row-pair? no: idx scheme below)
    // A tile: 1024 float4 -> 4 per thread: idx = tid + 256*i, r = idx>>3, c4 = idx&7
    // B tile: 1024 float4 -> 4 per thread: idx = tid + 256*i, r = idx>>5, c4 = idx&31
    (void)aR;

    auto load_tile = [&](int t, int p) {
        const int k0 = t * 32;
        const uint32_t Ab = sbase + p * BUF_BYTES;
        const uint32_t Bb = Ab + A_BYTES;
        #pragma unroll
        for (int i = 0; i < 4; i++) {
            int idx = tid + 256 * i;
            int r = idx >> 3, c4 = idx & 7;
            CP_ASYNC16(Ab + (uint32_t)(r * (A_STRIDE * 4) + c4 * 16),
                       &A[(rowBase + r) * K + k0 + c4 * 4]);
        }
        #pragma unroll
        for (int i = 0; i < 4; i++) {
            int idx = tid + 256 * i;
            int r = idx >> 5, c4 = idx & 31;
            CP_ASYNC16(Bb + (uint32_t)(r * (B_STRIDE * 4) + c4 * 16),
                       &B[(long)(k0 + r) * N + colBase + c4 * 4]);
        }
        CP_COMMIT();
    };

    float c[4][4][4];
    #pragma unroll
    for (int mb = 0; mb < 4; mb++)
        #pragma unroll
        for (int nb = 0; nb < 4; nb++)
            #pragma unroll
            for (int i = 0; i < 4; i++) c[mb][nb][i] = 0.0f;

    const int NT = K / 32;   // 32

    // Prologue: tiles 0 and 1 in flight
    load_tile(0, 0);
    load_tile(1, 1);

    for (int t = 0; t < NT; t++) {
        const int p = t & 1;
        if (t < NT - 1) { CP_WAIT(1); } else { CP_WAIT(0); }
        __syncthreads();

        const float* As = (const float*)(smem + p * BUF_BYTES);
        const float* Bs = (const float*)(smem + p * BUF_BYTES + A_BYTES);

        #pragma unroll
        for (int ks = 0; ks < 4; ks++) {
            const int kb = ks * 8;
            uint32_t af[4][4], bf[4][2];
            #pragma unroll
            for (int mb = 0; mb < 4; mb++) {
                const int base = (wm * 64 + mb * 16 + grp) * A_STRIDE + kb + tig;
                af[mb][0] = f2tf32(As[base]);
                af[mb][1] = f2tf32(As[base + 8 * A_STRIDE]);
                af[mb][2] = f2tf32(As[base + 4]);
                af[mb][3] = f2tf32(As[base + 8 * A_STRIDE + 4]);
            }
            #pragma unroll
            for (int nb = 0; nb < 4; nb++) {
                const int col = wn * 32 + nb * 8 + grp;
                const int boff = (kb + tig) * B_STRIDE + col;
                bf[nb][0] = f2tf32(Bs[boff]);
                bf[nb][1] = f2tf32(Bs[boff + 4 * B_STRIDE]);
            }
            #pragma unroll
            for (int mb = 0; mb < 4; mb++)
                #pragma unroll
                for (int nb = 0; nb < 4; nb++)
                    mma_tf32(c[mb][nb][0], c[mb][nb][1], c[mb][nb][2], c[mb][nb][3],
                             af[mb][0], af[mb][1], af[mb][2], af[mb][3],
                             bf[nb][0], bf[nb][1]);
        }

        __syncthreads();
        if (t + 2 < NT) load_tile(t + 2, p);
    }

    // Epilogue: c frags -> global with bias
    #pragma unroll
    for (int mb = 0; mb < 4; mb++) {
        const long r0 = rowBase + wm * 64 + mb * 16 + grp;
        #pragma unroll
        for (int nb = 0; nb < 4; nb++) {
            const int cc = (int)colBase + wn * 32 + nb * 8 + 2 * tig;
            const float bx = bias[cc], by = bias[cc + 1];
            float2 v0 = make_float2(c[mb][nb][0] + bx, c[mb][nb][1] + by);
            float2 v1 = make_float2(c[mb][nb][2] + bx, c[mb][nb][3] + by);
            *(float2*)&C[r0 * N + cc]       = v0;
            *(float2*)&C[(r0 + 8) * N + cc] = v1;
        }
    }
}

// ---------------------------------------------------------------------------
// Flash attention (fp32, causal) — unchanged (known correct).
// ---------------------------------------------------------------------------
__global__ __launch_bounds__(64)
void flash_attn(const float* __restrict__ qkv, float* __restrict__ y) {
    const int BQ = 64, BK = 64, NE = HDIM;
    const int qb = blockIdx.x;
    const int h  = blockIdx.y;
    const int b  = blockIdx.z;
    const int tid = threadIdx.x;
    const int qrow = qb * BQ + tid;
    const float scale = 0.125f;

    __shared__ float Ks[BK][NE];
    __shared__ float Vs[BK][NE];
    __shared__ float Ss[BK][BQ];

    float q[NE];
    const float* qptr = qkv + ((long)b * SEQ + qrow) * QKV_C + h * NE;
    #pragma unroll
    for (int e = 0; e < NE; e += 4) {
        float4 v = *(const float4*)&qptr[e];
        q[e + 0] = v.x * scale;
        q[e + 1] = v.y * scale;
        q[e + 2] = v.z * scale;
        q[e + 3] = v.w * scale;
    }

    float acc[NE];
    #pragma unroll
    for (int e = 0; e < NE; e++) acc[e] = 0.0f;
    float m = -INFINITY, l = 0.0f;

    const int nkb = qb + 1;
    for (int kb = 0; kb < nkb; kb++) {
        const float* kbase = qkv + ((long)b * SEQ + kb * BK + tid) * QKV_C + EMBD + h * NE;
        const float* vbase = kbase + EMBD;
        #pragma unroll
        for (int e = 0; e < NE; e += 4) {
            *(float4*)&Ks[tid][e] = *(const float4*)&kbase[e];
            *(float4*)&Vs[tid][e] = *(const float4*)&vbase[e];
        }
        __syncthreads();

        const int jmax = (kb == qb) ? (tid + 1) : BK;

        float newm = m;
        for (int j = 0; j < jmax; j++) {
            float s = 0.0f;
            #pragma unroll
            for (int e = 0; e < NE; e += 4) {
                float4 kv = *(const float4*)&Ks[j][e];
                s = fmaf(q[e + 0], kv.x, s);
                s = fmaf(q[e + 1], kv.y, s);
                s = fmaf(q[e + 2], kv.z, s);
                s = fmaf(q[e + 3], kv.w, s);
            }
            Ss[j][tid] = s;
            newm = fmaxf(newm, s);
        }

        const float corr = __expf(m - newm);
        l *= corr;
        #pragma unroll
        for (int e = 0; e < NE; e++) acc[e] *= corr;
        for (int j = 0; j < jmax; j++) {
            const float p = __expf(Ss[j][tid] - newm);
            l += p;
            #pragma unroll
            for (int e = 0; e < NE; e += 4) {
                float4 vv = *(const float4*)&Vs[j][e];
                acc[e + 0] = fmaf(p, vv.x, acc[e + 0]);
                acc[e + 1] = fmaf(p, vv.y, acc[e + 1]);
                acc[e + 2] = fmaf(p, vv.z, acc[e + 2]);
                acc[e + 3] = fmaf(p, vv.w, acc[e + 3]);
            }
        }
        m = newm;
        __syncthreads();
    }

    const float inv_l = 1.0f / l;
    float* optr = y + ((long)b * SEQ + qrow) * EMBD + h * NE;
    #pragma unroll
    for (int e = 0; e < NE; e += 4) {
        float4 o;
        o.x = acc[e + 0] * inv_l;
        o.y = acc[e + 1] * inv_l;
        o.z = acc[e + 2] * inv_l;
        o.w = acc[e + 3] * inv_l;
        *(float4*)&optr[e] = o;
    }
}

// ---------------------------------------------------------------------------
extern "C" void kernel_launch(void* const* d_in, const int* in_sizes, int n_in,
                              void* d_out, int out_size) {
    const float* x      = (const float*)d_in[0];
    const float* W_attn = (const float*)d_in[1];
    const float* b_attn = (const float*)d_in[2];
    const float* W_proj = (const float*)d_in[3];
    const float* b_proj = (const float*)d_in[4];
    float* out = (float*)d_out;

    float* qkv;
    float* y;
    cudaGetSymbolAddress((void**)&qkv, g_qkv);
    cudaGetSymbolAddress((void**)&y, g_y);

    const int M = BATCH * SEQ;  // 8192

    cudaFuncSetAttribute(gemm_tf32, cudaFuncAttributeMaxDynamicSharedMemorySize, SMEM_BYTES);

    // 1) QKV projection: [8192,1024] @ [1024,3072] + b_attn
    {
        dim3 grid(QKV_C / 128, M / 128);
        gemm_tf32<<<grid, 256, SMEM_BYTES>>>(x, W_attn, b_attn, qkv, M, QKV_C, EMBD);
    }

    // 2) Causal flash attention
    {
        dim3 grid(SEQ / 64, NHEAD, BATCH);
        flash_attn<<<grid, 64>>>(qkv, y);
    }

    // 3) Output projection: [8192,1024] @ [1024,1024] + b_proj
    {
        dim3 grid(EMBD / 128, M / 128);
        gemm_tf32<<<grid, 256, SMEM_BYTES>>>(y, W_proj, b_proj, out, M, EMBD, EMBD);
    }
}

// round 4
// speedup vs baseline: 3.9909x; 2.7552x over previous
#include <cuda_runtime.h>
#include <math.h>
#include <stdint.h>

// Problem constants
#define BATCH 4
#define SEQ   2048
#define EMBD  1024
#define NHEAD 16
#define HDIM  64
#define QKV_C (3 * EMBD)
#define LOG2E 1.4426950408889634f

// Scratch (device globals — no allocation allowed)
__device__ float g_qkv[BATCH * SEQ * QKV_C];
__device__ float g_y[BATCH * SEQ * EMBD];

// ---------------------------------------------------------------------------
// Helpers
// ---------------------------------------------------------------------------
__device__ __forceinline__ uint32_t smem_u32(const void* p) {
    uint32_t a;
    asm("{ .reg .u64 t; cvta.to.shared.u64 t, %1; cvt.u32.u64 %0, t; }" : "=r"(a) : "l"(p));
    return a;
}
__device__ __forceinline__ uint32_t f2tf32(float f) {
    uint32_t o;
    asm("cvt.rna.tf32.f32 %0, %1;" : "=r"(o) : "f"(f));
    return o;
}
__device__ __forceinline__ float ex2f(float x) {
    float y;
    asm("ex2.approx.f32 %0, %1;" : "=f"(y) : "f"(x));
    return y;
}
// pack (lo, hi) floats into bf16x2 (lo in low 16 bits)
__device__ __forceinline__ uint32_t pack_bf16(float lo, float hi) {
    uint32_t r;
    asm("cvt.rn.bf16x2.f32 %0, %1, %2;" : "=r"(r) : "f"(hi), "f"(lo));
    return r;
}
// split (x,y) into bf16 hi pair + bf16 lo (residual) pair
__device__ __forceinline__ void split_pack(float x, float y, uint32_t& hi, uint32_t& lo) {
    uint32_t h = pack_bf16(x, y);
    float hx = __uint_as_float(h << 16);
    float hy = __uint_as_float(h & 0xFFFF0000u);
    lo = pack_bf16(x - hx, y - hy);
    hi = h;
}
#define CP_ASYNC16(dst_u32, src_ptr) \
    asm volatile("cp.async.cg.shared.global [%0], [%1], 16;" :: "r"(dst_u32), "l"(src_ptr))
#define CP_COMMIT() asm volatile("cp.async.commit_group;" ::: "memory")
#define CP_WAIT(n)  asm volatile("cp.async.wait_group %0;" :: "n"(n) : "memory")

__device__ __forceinline__ void mma_tf32(float& c0, float& c1, float& c2, float& c3,
                                         uint32_t a0, uint32_t a1, uint32_t a2, uint32_t a3,
                                         uint32_t b0, uint32_t b1) {
    asm volatile(
        "mma.sync.aligned.m16n8k8.row.col.f32.tf32.tf32.f32 "
        "{%0,%1,%2,%3}, {%4,%5,%6,%7}, {%8,%9}, {%0,%1,%2,%3};"
        : "+f"(c0), "+f"(c1), "+f"(c2), "+f"(c3)
        : "r"(a0), "r"(a1), "r"(a2), "r"(a3), "r"(b0), "r"(b1));
}
__device__ __forceinline__ void mma_bf16(float* c, const uint32_t* a, uint32_t b0, uint32_t b1) {
    asm volatile(
        "mma.sync.aligned.m16n8k16.row.col.f32.bf16.bf16.f32 "
        "{%0,%1,%2,%3}, {%4,%5,%6,%7}, {%8,%9}, {%0,%1,%2,%3};"
        : "+f"(c[0]), "+f"(c[1]), "+f"(c[2]), "+f"(c[3])
        : "r"(a[0]), "r"(a[1]), "r"(a[2]), "r"(a[3]), "r"(b0), "r"(b1));
}

// ---------------------------------------------------------------------------
// TF32 mma.sync GEMM (unchanged from Round 3, known good)
// ---------------------------------------------------------------------------
#define A_STRIDE 36
#define B_STRIDE 136
#define A_BYTES  (128 * A_STRIDE * 4)
#define B_BYTES  (32 * B_STRIDE * 4)
#define BUF_BYTES (A_BYTES + B_BYTES)
#define SMEM_BYTES (2 * BUF_BYTES)

__global__ __launch_bounds__(256)
void gemm_tf32(const float* __restrict__ A, const float* __restrict__ B,
               const float* __restrict__ bias, float* __restrict__ C,
               int M, int N, int K) {
    extern __shared__ char smem[];
    const int tid  = threadIdx.x;
    const int wid  = tid >> 5;
    const int lane = tid & 31;
    const int wm   = wid >> 2;
    const int wn   = wid & 3;
    const int grp  = lane >> 2;
    const int tig  = lane & 3;

    const long rowBase = (long)blockIdx.y * 128;
    const long colBase = (long)blockIdx.x * 128;
    const uint32_t sbase = smem_u32(smem);

    auto load_tile = [&](int t, int p) {
        const int k0 = t * 32;
        const uint32_t Ab = sbase + p * BUF_BYTES;
        const uint32_t Bb = Ab + A_BYTES;
        #pragma unroll
        for (int i = 0; i < 4; i++) {
            int idx = tid + 256 * i;
            int r = idx >> 3, c4 = idx & 7;
            CP_ASYNC16(Ab + (uint32_t)(r * (A_STRIDE * 4) + c4 * 16),
                       &A[(rowBase + r) * K + k0 + c4 * 4]);
        }
        #pragma unroll
        for (int i = 0; i < 4; i++) {
            int idx = tid + 256 * i;
            int r = idx >> 5, c4 = idx & 31;
            CP_ASYNC16(Bb + (uint32_t)(r * (B_STRIDE * 4) + c4 * 16),
                       &B[(long)(k0 + r) * N + colBase + c4 * 4]);
        }
        CP_COMMIT();
    };

    float c[4][4][4];
    #pragma unroll
    for (int mb = 0; mb < 4; mb++)
        #pragma unroll
        for (int nb = 0; nb < 4; nb++)
            #pragma unroll
            for (int i = 0; i < 4; i++) c[mb][nb][i] = 0.0f;

    const int NT = K / 32;

    load_tile(0, 0);
    load_tile(1, 1);

    for (int t = 0; t < NT; t++) {
        const int p = t & 1;
        if (t < NT - 1) { CP_WAIT(1); } else { CP_WAIT(0); }
        __syncthreads();

        const float* As = (const float*)(smem + p * BUF_BYTES);
        const float* Bs = (const float*)(smem + p * BUF_BYTES + A_BYTES);

        #pragma unroll
        for (int ks = 0; ks < 4; ks++) {
            const int kb = ks * 8;
            uint32_t af[4][4], bf[4][2];
            #pragma unroll
            for (int mb = 0; mb < 4; mb++) {
                const int base = (wm * 64 + mb * 16 + grp) * A_STRIDE + kb + tig;
                af[mb][0] = f2tf32(As[base]);
                af[mb][1] = f2tf32(As[base + 8 * A_STRIDE]);
                af[mb][2] = f2tf32(As[base + 4]);
                af[mb][3] = f2tf32(As[base + 8 * A_STRIDE + 4]);
            }
            #pragma unroll
            for (int nb = 0; nb < 4; nb++) {
                const int col = wn * 32 + nb * 8 + grp;
                const int boff = (kb + tig) * B_STRIDE + col;
                bf[nb][0] = f2tf32(Bs[boff]);
                bf[nb][1] = f2tf32(Bs[boff + 4 * B_STRIDE]);
            }
            #pragma unroll
            for (int mb = 0; mb < 4; mb++)
                #pragma unroll
                for (int nb = 0; nb < 4; nb++)
                    mma_tf32(c[mb][nb][0], c[mb][nb][1], c[mb][nb][2], c[mb][nb][3],
                             af[mb][0], af[mb][1], af[mb][2], af[mb][3],
                             bf[nb][0], bf[nb][1]);
        }

        __syncthreads();
        if (t + 2 < NT) load_tile(t + 2, p);
    }

    #pragma unroll
    for (int mb = 0; mb < 4; mb++) {
        const long r0 = rowBase + wm * 64 + mb * 16 + grp;
        #pragma unroll
        for (int nb = 0; nb < 4; nb++) {
            const int cc = (int)colBase + wn * 32 + nb * 8 + 2 * tig;
            const float bx = bias[cc], by = bias[cc + 1];
            float2 v0 = make_float2(c[mb][nb][0] + bx, c[mb][nb][1] + by);
            float2 v1 = make_float2(c[mb][nb][2] + bx, c[mb][nb][3] + by);
            *(float2*)&C[r0 * N + cc]       = v0;
            *(float2*)&C[(r0 + 8) * N + cc] = v1;
        }
    }
}

// ---------------------------------------------------------------------------
// MMA flash attention (causal). CTA = 128 q rows x head x batch. 8 warps,
// warp owns 16 q rows. KV-tile = 64.
//   QK^T : split-bf16 3-term mma (fp32-accurate scores)
//   P@V  : tf32 mma
// ---------------------------------------------------------------------------
#define KST 36   // K smem row stride (u32): 32 data + 4 pad -> conflict-free frags
#define VST 68   // V smem row stride (u32): 64 data + 4 pad

__global__ __launch_bounds__(256, 2)
void flash_attn_mma(const float* __restrict__ qkv, float* __restrict__ y) {
    const int qb = blockIdx.x, h = blockIdx.y, b = blockIdx.z;
    const int tid = threadIdx.x, wid = tid >> 5, lane = tid & 31;
    const int grp = lane >> 2, tig = lane & 3;

    __shared__ uint32_t Khi[64 * KST];
    __shared__ uint32_t Klo[64 * KST];
    __shared__ uint32_t Vsm[64 * VST];

    const int qrow0 = qb * 128 + wid * 16;
    const long bS = (long)b * SEQ;

    // --- Q fragments (bf16 hi/lo, pre-scaled by 1/sqrt(64)) ---
    uint32_t qh[4][4], ql[4][4];
    {
        const long r0 = bS + qrow0 + grp;
        const long r1 = r0 + 8;
        #pragma unroll
        for (int ec = 0; ec < 4; ec++) {
            const int c = h * HDIM + 16 * ec + 2 * tig;
            float2 v00 = *(const float2*)&qkv[r0 * QKV_C + c];
            float2 v10 = *(const float2*)&qkv[r1 * QKV_C + c];
            float2 v01 = *(const float2*)&qkv[r0 * QKV_C + c + 8];
            float2 v11 = *(const float2*)&qkv[r1 * QKV_C + c + 8];
            split_pack(v00.x * 0.125f, v00.y * 0.125f, qh[ec][0], ql[ec][0]);
            split_pack(v10.x * 0.125f, v10.y * 0.125f, qh[ec][1], ql[ec][1]);
            split_pack(v01.x * 0.125f, v01.y * 0.125f, qh[ec][2], ql[ec][2]);
            split_pack(v11.x * 0.125f, v11.y * 0.125f, qh[ec][3], ql[ec][3]);
        }
    }

    float acc[8][4];
    #pragma unroll
    for (int eb = 0; eb < 8; eb++)
        #pragma unroll
        for (int i = 0; i < 4; i++) acc[eb][i] = 0.0f;
    float m0 = -1e30f, m1 = -1e30f, l0 = 0.0f, l1 = 0.0f;

    const int ntile = 2 * qb + 2;
    for (int kt = 0; kt < ntile; kt++) {
        __syncthreads();
        const int j0 = kt * 64;
        {
            // cooperative load + convert: K -> bf16 hi/lo packed, V -> tf32
            const float* kg = qkv + (bS + j0) * QKV_C + EMBD + h * HDIM;
            const float* vg = kg + EMBD;
            #pragma unroll
            for (int i = 0; i < 4; i++) {
                const int idx = tid + 256 * i;
                const int r = idx >> 4, c4 = idx & 15;
                float4 k4 = *(const float4*)&kg[(long)r * QKV_C + c4 * 4];
                uint32_t h0, u0, h1, u1;
                split_pack(k4.x, k4.y, h0, u0);
                split_pack(k4.z, k4.w, h1, u1);
                *(uint2*)&Khi[r * KST + c4 * 2] = make_uint2(h0, h1);
                *(uint2*)&Klo[r * KST + c4 * 2] = make_uint2(u0, u1);
                float4 v4 = *(const float4*)&vg[(long)r * QKV_C + c4 * 4];
                *(uint4*)&Vsm[r * VST + c4 * 4] =
                    make_uint4(f2tf32(v4.x), f2tf32(v4.y), f2tf32(v4.z), f2tf32(v4.w));
            }
        }
        __syncthreads();

        if (j0 > qrow0 + 15) continue;          // fully masked for this warp
        const bool diag = (j0 + 63 > qrow0);    // needs elementwise mask

        // --- S = Q K^T (3-term split-bf16) ---
        float s[8][4];
        #pragma unroll
        for (int jb = 0; jb < 8; jb++) {
            s[jb][0] = s[jb][1] = s[jb][2] = s[jb][3] = 0.0f;
            const int kr = (8 * jb + grp) * KST;
            #pragma unroll
            for (int ec = 0; ec < 4; ec++) {
                const uint32_t bh0 = Khi[kr + 8 * ec + tig];
                const uint32_t bh1 = Khi[kr + 8 * ec + tig + 4];
                const uint32_t bl0 = Klo[kr + 8 * ec + tig];
                const uint32_t bl1 = Klo[kr + 8 * ec + tig + 4];
                mma_bf16(s[jb], qh[ec], bh0, bh1);
                mma_bf16(s[jb], qh[ec], bl0, bl1);
                mma_bf16(s[jb], ql[ec], bh0, bh1);
            }
        }

        if (diag) {
            const int i0r = qrow0 + grp, i1r = i0r + 8;
            #pragma unroll
            for (int jb = 0; jb < 8; jb++) {
                const int j = j0 + 8 * jb + 2 * tig;
                if (j     > i0r) s[jb][0] = -1e30f;
                if (j + 1 > i0r) s[jb][1] = -1e30f;
                if (j     > i1r) s[jb][2] = -1e30f;
                if (j + 1 > i1r) s[jb][3] = -1e30f;
            }
        }

        // --- online softmax ---
        float rm0 = -1e30f, rm1 = -1e30f;
        #pragma unroll
        for (int jb = 0; jb < 8; jb++) {
            rm0 = fmaxf(rm0, fmaxf(s[jb][0], s[jb][1]));
            rm1 = fmaxf(rm1, fmaxf(s[jb][2], s[jb][3]));
        }
        rm0 = fmaxf(rm0, __shfl_xor_sync(0xffffffffu, rm0, 1));
        rm0 = fmaxf(rm0, __shfl_xor_sync(0xffffffffu, rm0, 2));
        rm1 = fmaxf(rm1, __shfl_xor_sync(0xffffffffu, rm1, 1));
        rm1 = fmaxf(rm1, __shfl_xor_sync(0xffffffffu, rm1, 2));
        const float nm0 = fmaxf(m0, rm0), nm1 = fmaxf(m1, rm1);

        float sum0 = 0.0f, sum1 = 0.0f;
        #pragma unroll
        for (int jb = 0; jb < 8; jb++) {
            s[jb][0] = ex2f((s[jb][0] - nm0) * LOG2E);
            s[jb][1] = ex2f((s[jb][1] - nm0) * LOG2E);
            s[jb][2] = ex2f((s[jb][2] - nm1) * LOG2E);
            s[jb][3] = ex2f((s[jb][3] - nm1) * LOG2E);
            sum0 += s[jb][0] + s[jb][1];
            sum1 += s[jb][2] + s[jb][3];
        }
        sum0 += __shfl_xor_sync(0xffffffffu, sum0, 1);
        sum0 += __shfl_xor_sync(0xffffffffu, sum0, 2);
        sum1 += __shfl_xor_sync(0xffffffffu, sum1, 1);
        sum1 += __shfl_xor_sync(0xffffffffu, sum1, 2);

        const float cr0 = ex2f((m0 - nm0) * LOG2E);
        const float cr1 = ex2f((m1 - nm1) * LOG2E);
        l0 = l0 * cr0 + sum0;
        l1 = l1 * cr1 + sum1;
        m0 = nm0;
        m1 = nm1;
        #pragma unroll
        for (int eb = 0; eb < 8; eb++) {
            acc[eb][0] *= cr0; acc[eb][1] *= cr0;
            acc[eb][2] *= cr1; acc[eb][3] *= cr1;
        }

        // convert P to tf32 in place
        #pragma unroll
        for (int jb = 0; jb < 8; jb++) {
            s[jb][0] = __uint_as_float(f2tf32(s[jb][0]));
            s[jb][1] = __uint_as_float(f2tf32(s[jb][1]));
            s[jb][2] = __uint_as_float(f2tf32(s[jb][2]));
            s[jb][3] = __uint_as_float(f2tf32(s[jb][3]));
        }

        // --- y += P @ V (tf32) ---
        const int src0 = 4 * grp + (tig >> 1);
        const int src1 = src0 + 2;
        const bool odd = (tig & 1);
        #pragma unroll
        for (int kc = 0; kc < 8; kc++) {
            float x0 = __shfl_sync(0xffffffffu, s[kc][0], src0);
            float x1 = __shfl_sync(0xffffffffu, s[kc][1], src0);
            const uint32_t a0 = __float_as_uint(odd ? x1 : x0);
            x0 = __shfl_sync(0xffffffffu, s[kc][2], src0);
            x1 = __shfl_sync(0xffffffffu, s[kc][3], src0);
            const uint32_t a1 = __float_as_uint(odd ? x1 : x0);
            x0 = __shfl_sync(0xffffffffu, s[kc][0], src1);
            x1 = __shfl_sync(0xffffffffu, s[kc][1], src1);
            const uint32_t a2 = __float_as_uint(odd ? x1 : x0);
            x0 = __shfl_sync(0xffffffffu, s[kc][2], src1);
            x1 = __shfl_sync(0xffffffffu, s[kc][3], src1);
            const uint32_t a3 = __float_as_uint(odd ? x1 : x0);

            const int vr0 = (8 * kc + tig) * VST;
            const int vr1 = (8 * kc + tig + 4) * VST;
            #pragma unroll
            for (int eb = 0; eb < 8; eb++) {
                const uint32_t b0 = Vsm[vr0 + 8 * eb + grp];
                const uint32_t b1 = Vsm[vr1 + 8 * eb + grp];
                mma_tf32(acc[eb][0], acc[eb][1], acc[eb][2], acc[eb][3],
                         a0, a1, a2, a3, b0, b1);
            }
        }
    }

    // --- epilogue ---
    const float inv0 = 1.0f / l0, inv1 = 1.0f / l1;
    const long r0 = bS + qrow0 + grp;
    const long r1 = r0 + 8;
    #pragma unroll
    for (int eb = 0; eb < 8; eb++) {
        const int c = h * HDIM + 8 * eb + 2 * tig;
        *(float2*)&y[r0 * EMBD + c] = make_float2(acc[eb][0] * inv0, acc[eb][1] * inv0);
        *(float2*)&y[r1 * EMBD + c] = make_float2(acc[eb][2] * inv1, acc[eb][3] * inv1);
    }
}

// ---------------------------------------------------------------------------
extern "C" void kernel_launch(void* const* d_in, const int* in_sizes, int n_in,
                              void* d_out, int out_size) {
    const float* x      = (const float*)d_in[0];
    const float* W_attn = (const float*)d_in[1];
    const float* b_attn = (const float*)d_in[2];
    const float* W_proj = (const float*)d_in[3];
    const float* b_proj = (const float*)d_in[4];
    float* out = (float*)d_out;

    float* qkv;
    float* y;
    cudaGetSymbolAddress((void**)&qkv, g_qkv);
    cudaGetSymbolAddress((void**)&y, g_y);

    const int M = BATCH * SEQ;  // 8192

    cudaFuncSetAttribute(gemm_tf32, cudaFuncAttributeMaxDynamicSharedMemorySize, SMEM_BYTES);

    // 1) QKV projection
    {
        dim3 grid(QKV_C / 128, M / 128);
        gemm_tf32<<<grid, 256, SMEM_BYTES>>>(x, W_attn, b_attn, qkv, M, QKV_C, EMBD);
    }

    // 2) Causal flash attention (MMA)
    {
        dim3 grid(SEQ / 128, NHEAD, BATCH);
        flash_attn_mma<<<grid, 256>>>(qkv, y);
    }

    // 3) Output projection
    {
        dim3 grid(EMBD / 128, M / 128);
        gemm_tf32<<<grid, 256, SMEM_BYTES>>>(y, W_proj, b_proj, out, M, EMBD, EMBD);
    }
}

// round 5
// speedup vs baseline: 4.2351x; 1.0612x over previous
#include <cuda_runtime.h>
#include <math.h>
#include <stdint.h>

// Problem constants
#define BATCH 4
#define SEQ   2048
#define EMBD  1024
#define NHEAD 16
#define HDIM  64
#define QKV_C (3 * EMBD)
#define LOG2E 1.4426950408889634f

// Scratch (device globals — no allocation allowed)
__device__ float g_qkv[BATCH * SEQ * QKV_C];
__device__ float g_y[BATCH * SEQ * EMBD];

// ---------------------------------------------------------------------------
// Helpers
// ---------------------------------------------------------------------------
__device__ __forceinline__ uint32_t smem_u32(const void* p) {
    uint32_t a;
    asm("{ .reg .u64 t; cvta.to.shared.u64 t, %1; cvt.u32.u64 %0, t; }" : "=r"(a) : "l"(p));
    return a;
}
__device__ __forceinline__ uint32_t f2tf32(float f) {
    uint32_t o;
    asm("cvt.rna.tf32.f32 %0, %1;" : "=r"(o) : "f"(f));
    return o;
}
__device__ __forceinline__ float ex2f(float x) {
    float y;
    asm("ex2.approx.f32 %0, %1;" : "=f"(y) : "f"(x));
    return y;
}
// pack (lo, hi) floats into bf16x2 (lo in low 16 bits)
__device__ __forceinline__ uint32_t pack_bf16(float lo, float hi) {
    uint32_t r;
    asm("cvt.rn.bf16x2.f32 %0, %1, %2;" : "=r"(r) : "f"(hi), "f"(lo));
    return r;
}
// split (x,y) into bf16 hi pair + bf16 lo (residual) pair
__device__ __forceinline__ void split_pack(float x, float y, uint32_t& hi, uint32_t& lo) {
    uint32_t h = pack_bf16(x, y);
    float hx = __uint_as_float(h << 16);
    float hy = __uint_as_float(h & 0xFFFF0000u);
    lo = pack_bf16(x - hx, y - hy);
    hi = h;
}
#define CP_ASYNC16(dst_u32, src_ptr) \
    asm volatile("cp.async.cg.shared.global [%0], [%1], 16;" :: "r"(dst_u32), "l"(src_ptr))
#define CP_COMMIT() asm volatile("cp.async.commit_group;" ::: "memory")
#define CP_WAIT(n)  asm volatile("cp.async.wait_group %0;" :: "n"(n) : "memory")

__device__ __forceinline__ void mma_tf32(float& c0, float& c1, float& c2, float& c3,
                                         uint32_t a0, uint32_t a1, uint32_t a2, uint32_t a3,
                                         uint32_t b0, uint32_t b1) {
    asm volatile(
        "mma.sync.aligned.m16n8k8.row.col.f32.tf32.tf32.f32 "
        "{%0,%1,%2,%3}, {%4,%5,%6,%7}, {%8,%9}, {%0,%1,%2,%3};"
        : "+f"(c0), "+f"(c1), "+f"(c2), "+f"(c3)
        : "r"(a0), "r"(a1), "r"(a2), "r"(a3), "r"(b0), "r"(b1));
}
__device__ __forceinline__ void mma_bf16(float* c, const uint32_t* a, uint32_t b0, uint32_t b1) {
    asm volatile(
        "mma.sync.aligned.m16n8k16.row.col.f32.bf16.bf16.f32 "
        "{%0,%1,%2,%3}, {%4,%5,%6,%7}, {%8,%9}, {%0,%1,%2,%3};"
        : "+f"(c[0]), "+f"(c[1]), "+f"(c[2]), "+f"(c[3])
        : "r"(a[0]), "r"(a[1]), "r"(a[2]), "r"(a[3]), "r"(b0), "r"(b1));
}

// ---------------------------------------------------------------------------
// TF32 mma.sync GEMM: C[M,N] = A[M,K] @ B[K,N] + bias[N]
// CTA 128x128, BK=32, 256 threads, double-buffered cp.async.
// launch_bounds(256, 2): cap regs at 128 so 2 CTAs/SM fit the register file.
// ---------------------------------------------------------------------------
#define A_STRIDE 36
#define B_STRIDE 136
#define A_BYTES  (128 * A_STRIDE * 4)
#define B_BYTES  (32 * B_STRIDE * 4)
#define BUF_BYTES (A_BYTES + B_BYTES)
#define SMEM_BYTES (2 * BUF_BYTES)

__global__ __launch_bounds__(256, 2)
void gemm_tf32(const float* __restrict__ A, const float* __restrict__ B,
               const float* __restrict__ bias, float* __restrict__ C,
               int M, int N, int K) {
    extern __shared__ char smem[];
    const int tid  = threadIdx.x;
    const int wid  = tid >> 5;
    const int lane = tid & 31;
    const int wm   = wid >> 2;
    const int wn   = wid & 3;
    const int grp  = lane >> 2;
    const int tig  = lane & 3;

    const long rowBase = (long)blockIdx.y * 128;
    const long colBase = (long)blockIdx.x * 128;
    const uint32_t sbase = smem_u32(smem);

    auto load_tile = [&](int t, int p) {
        const int k0 = t * 32;
        const uint32_t Ab = sbase + p * BUF_BYTES;
        const uint32_t Bb = Ab + A_BYTES;
        #pragma unroll
        for (int i = 0; i < 4; i++) {
            int idx = tid + 256 * i;
            int r = idx >> 3, c4 = idx & 7;
            CP_ASYNC16(Ab + (uint32_t)(r * (A_STRIDE * 4) + c4 * 16),
                       &A[(rowBase + r) * K + k0 + c4 * 4]);
        }
        #pragma unroll
        for (int i = 0; i < 4; i++) {
            int idx = tid + 256 * i;
            int r = idx >> 5, c4 = idx & 31;
            CP_ASYNC16(Bb + (uint32_t)(r * (B_STRIDE * 4) + c4 * 16),
                       &B[(long)(k0 + r) * N + colBase + c4 * 4]);
        }
        CP_COMMIT();
    };

    float c[4][4][4];
    #pragma unroll
    for (int mb = 0; mb < 4; mb++)
        #pragma unroll
        for (int nb = 0; nb < 4; nb++)
            #pragma unroll
            for (int i = 0; i < 4; i++) c[mb][nb][i] = 0.0f;

    const int NT = K / 32;

    load_tile(0, 0);
    load_tile(1, 1);

    for (int t = 0; t < NT; t++) {
        const int p = t & 1;
        if (t < NT - 1) { CP_WAIT(1); } else { CP_WAIT(0); }
        __syncthreads();

        const float* As = (const float*)(smem + p * BUF_BYTES);
        const float* Bs = (const float*)(smem + p * BUF_BYTES + A_BYTES);

        #pragma unroll
        for (int ks = 0; ks < 4; ks++) {
            const int kb = ks * 8;
            uint32_t af[4][4], bf[4][2];
            #pragma unroll
            for (int mb = 0; mb < 4; mb++) {
                const int base = (wm * 64 + mb * 16 + grp) * A_STRIDE + kb + tig;
                af[mb][0] = f2tf32(As[base]);
                af[mb][1] = f2tf32(As[base + 8 * A_STRIDE]);
                af[mb][2] = f2tf32(As[base + 4]);
                af[mb][3] = f2tf32(As[base + 8 * A_STRIDE + 4]);
            }
            #pragma unroll
            for (int nb = 0; nb < 4; nb++) {
                const int col = wn * 32 + nb * 8 + grp;
                const int boff = (kb + tig) * B_STRIDE + col;
                bf[nb][0] = f2tf32(Bs[boff]);
                bf[nb][1] = f2tf32(Bs[boff + 4 * B_STRIDE]);
            }
            #pragma unroll
            for (int mb = 0; mb < 4; mb++)
                #pragma unroll
                for (int nb = 0; nb < 4; nb++)
                    mma_tf32(c[mb][nb][0], c[mb][nb][1], c[mb][nb][2], c[mb][nb][3],
                             af[mb][0], af[mb][1], af[mb][2], af[mb][3],
                             bf[nb][0], bf[nb][1]);
        }

        __syncthreads();
        if (t + 2 < NT) load_tile(t + 2, p);
    }

    #pragma unroll
    for (int mb = 0; mb < 4; mb++) {
        const long r0 = rowBase + wm * 64 + mb * 16 + grp;
        #pragma unroll
        for (int nb = 0; nb < 4; nb++) {
            const int cc = (int)colBase + wn * 32 + nb * 8 + 2 * tig;
            const float bx = bias[cc], by = bias[cc + 1];
            float2 v0 = make_float2(c[mb][nb][0] + bx, c[mb][nb][1] + by);
            float2 v1 = make_float2(c[mb][nb][2] + bx, c[mb][nb][3] + by);
            *(float2*)&C[r0 * N + cc]       = v0;
            *(float2*)&C[(r0 + 8) * N + cc] = v1;
        }
    }
}

// ---------------------------------------------------------------------------
// MMA flash attention (causal) — unchanged from Round 4 (known good).
// ---------------------------------------------------------------------------
#define KST 36
#define VST 68

__global__ __launch_bounds__(256, 2)
void flash_attn_mma(const float* __restrict__ qkv, float* __restrict__ y) {
    const int qb = blockIdx.x, h = blockIdx.y, b = blockIdx.z;
    const int tid = threadIdx.x, wid = tid >> 5, lane = tid & 31;
    const int grp = lane >> 2, tig = lane & 3;

    __shared__ uint32_t Khi[64 * KST];
    __shared__ uint32_t Klo[64 * KST];
    __shared__ uint32_t Vsm[64 * VST];

    const int qrow0 = qb * 128 + wid * 16;
    const long bS = (long)b * SEQ;

    uint32_t qh[4][4], ql[4][4];
    {
        const long r0 = bS + qrow0 + grp;
        const long r1 = r0 + 8;
        #pragma unroll
        for (int ec = 0; ec < 4; ec++) {
            const int c = h * HDIM + 16 * ec + 2 * tig;
            float2 v00 = *(const float2*)&qkv[r0 * QKV_C + c];
            float2 v10 = *(const float2*)&qkv[r1 * QKV_C + c];
            float2 v01 = *(const float2*)&qkv[r0 * QKV_C + c + 8];
            float2 v11 = *(const float2*)&qkv[r1 * QKV_C + c + 8];
            split_pack(v00.x * 0.125f, v00.y * 0.125f, qh[ec][0], ql[ec][0]);
            split_pack(v10.x * 0.125f, v10.y * 0.125f, qh[ec][1], ql[ec][1]);
            split_pack(v01.x * 0.125f, v01.y * 0.125f, qh[ec][2], ql[ec][2]);
            split_pack(v11.x * 0.125f, v11.y * 0.125f, qh[ec][3], ql[ec][3]);
        }
    }

    float acc[8][4];
    #pragma unroll
    for (int eb = 0; eb < 8; eb++)
        #pragma unroll
        for (int i = 0; i < 4; i++) acc[eb][i] = 0.0f;
    float m0 = -1e30f, m1 = -1e30f, l0 = 0.0f, l1 = 0.0f;

    const int ntile = 2 * qb + 2;
    for (int kt = 0; kt < ntile; kt++) {
        __syncthreads();
        const int j0 = kt * 64;
        {
            const float* kg = qkv + (bS + j0) * QKV_C + EMBD + h * HDIM;
            const float* vg = kg + EMBD;
            #pragma unroll
            for (int i = 0; i < 4; i++) {
                const int idx = tid + 256 * i;
                const int r = idx >> 4, c4 = idx & 15;
                float4 k4 = *(const float4*)&kg[(long)r * QKV_C + c4 * 4];
                uint32_t h0, u0, h1, u1;
                split_pack(k4.x, k4.y, h0, u0);
                split_pack(k4.z, k4.w, h1, u1);
                *(uint2*)&Khi[r * KST + c4 * 2] = make_uint2(h0, h1);
                *(uint2*)&Klo[r * KST + c4 * 2] = make_uint2(u0, u1);
                float4 v4 = *(const float4*)&vg[(long)r * QKV_C + c4 * 4];
                *(uint4*)&Vsm[r * VST + c4 * 4] =
                    make_uint4(f2tf32(v4.x), f2tf32(v4.y), f2tf32(v4.z), f2tf32(v4.w));
            }
        }
        __syncthreads();

        if (j0 > qrow0 + 15) continue;
        const bool diag = (j0 + 63 > qrow0);

        float s[8][4];
        #pragma unroll
        for (int jb = 0; jb < 8; jb++) {
            s[jb][0] = s[jb][1] = s[jb][2] = s[jb][3] = 0.0f;
            const int kr = (8 * jb + grp) * KST;
            #pragma unroll
            for (int ec = 0; ec < 4; ec++) {
                const uint32_t bh0 = Khi[kr + 8 * ec + tig];
                const uint32_t bh1 = Khi[kr + 8 * ec + tig + 4];
                const uint32_t bl0 = Klo[kr + 8 * ec + tig];
                const uint32_t bl1 = Klo[kr + 8 * ec + tig + 4];
                mma_bf16(s[jb], qh[ec], bh0, bh1);
                mma_bf16(s[jb], qh[ec], bl0, bl1);
                mma_bf16(s[jb], ql[ec], bh0, bh1);
            }
        }

        if (diag) {
            const int i0r = qrow0 + grp, i1r = i0r + 8;
            #pragma unroll
            for (int jb = 0; jb < 8; jb++) {
                const int j = j0 + 8 * jb + 2 * tig;
                if (j     > i0r) s[jb][0] = -1e30f;
                if (j + 1 > i0r) s[jb][1] = -1e30f;
                if (j     > i1r) s[jb][2] = -1e30f;
                if (j + 1 > i1r) s[jb][3] = -1e30f;
            }
        }

        float rm0 = -1e30f, rm1 = -1e30f;
        #pragma unroll
        for (int jb = 0; jb < 8; jb++) {
            rm0 = fmaxf(rm0, fmaxf(s[jb][0], s[jb][1]));
            rm1 = fmaxf(rm1, fmaxf(s[jb][2], s[jb][3]));
        }
        rm0 = fmaxf(rm0, __shfl_xor_sync(0xffffffffu, rm0, 1));
        rm0 = fmaxf(rm0, __shfl_xor_sync(0xffffffffu, rm0, 2));
        rm1 = fmaxf(rm1, __shfl_xor_sync(0xffffffffu, rm1, 1));
        rm1 = fmaxf(rm1, __shfl_xor_sync(0xffffffffu, rm1, 2));
        const float nm0 = fmaxf(m0, rm0), nm1 = fmaxf(m1, rm1);

        float sum0 = 0.0f, sum1 = 0.0f;
        #pragma unroll
        for (int jb = 0; jb < 8; jb++) {
            s[jb][0] = ex2f((s[jb][0] - nm0) * LOG2E);
            s[jb][1] = ex2f((s[jb][1] - nm0) * LOG2E);
            s[jb][2] = ex2f((s[jb][2] - nm1) * LOG2E);
            s[jb][3] = ex2f((s[jb][3] - nm1) * LOG2E);
            sum0 += s[jb][0] + s[jb][1];
            sum1 += s[jb][2] + s[jb][3];
        }
        sum0 += __shfl_xor_sync(0xffffffffu, sum0, 1);
        sum0 += __shfl_xor_sync(0xffffffffu, sum0, 2);
        sum1 += __shfl_xor_sync(0xffffffffu, sum1, 1);
        sum1 += __shfl_xor_sync(0xffffffffu, sum1, 2);

        const float cr0 = ex2f((m0 - nm0) * LOG2E);
        const float cr1 = ex2f((m1 - nm1) * LOG2E);
        l0 = l0 * cr0 + sum0;
        l1 = l1 * cr1 + sum1;
        m0 = nm0;
        m1 = nm1;
        #pragma unroll
        for (int eb = 0; eb < 8; eb++) {
            acc[eb][0] *= cr0; acc[eb][1] *= cr0;
            acc[eb][2] *= cr1; acc[eb][3] *= cr1;
        }

        #pragma unroll
        for (int jb = 0; jb < 8; jb++) {
            s[jb][0] = __uint_as_float(f2tf32(s[jb][0]));
            s[jb][1] = __uint_as_float(f2tf32(s[jb][1]));
            s[jb][2] = __uint_as_float(f2tf32(s[jb][2]));
            s[jb][3] = __uint_as_float(f2tf32(s[jb][3]));
        }

        const int src0 = 4 * grp + (tig >> 1);
        const int src1 = src0 + 2;
        const bool odd = (tig & 1);
        #pragma unroll
        for (int kc = 0; kc < 8; kc++) {
            float x0 = __shfl_sync(0xffffffffu, s[kc][0], src0);
            float x1 = __shfl_sync(0xffffffffu, s[kc][1], src0);
            const uint32_t a0 = __float_as_uint(odd ? x1 : x0);
            x0 = __shfl_sync(0xffffffffu, s[kc][2], src0);
            x1 = __shfl_sync(0xffffffffu, s[kc][3], src0);
            const uint32_t a1 = __float_as_uint(odd ? x1 : x0);
            x0 = __shfl_sync(0xffffffffu, s[kc][0], src1);
            x1 = __shfl_sync(0xffffffffu, s[kc][1], src1);
            const uint32_t a2 = __float_as_uint(odd ? x1 : x0);
            x0 = __shfl_sync(0xffffffffu, s[kc][2], src1);
            x1 = __shfl_sync(0xffffffffu, s[kc][3], src1);
            const uint32_t a3 = __float_as_uint(odd ? x1 : x0);

            const int vr0 = (8 * kc + tig) * VST;
            const int vr1 = (8 * kc + tig + 4) * VST;
            #pragma unroll
            for (int eb = 0; eb < 8; eb++) {
                const uint32_t b0 = Vsm[vr0 + 8 * eb + grp];
                const uint32_t b1 = Vsm[vr1 + 8 * eb + grp];
                mma_tf32(acc[eb][0], acc[eb][1], acc[eb][2], acc[eb][3],
                         a0, a1, a2, a3, b0, b1);
            }
        }
    }

    const float inv0 = 1.0f / l0, inv1 = 1.0f / l1;
    const long r0 = bS + qrow0 + grp;
    const long r1 = r0 + 8;
    #pragma unroll
    for (int eb = 0; eb < 8; eb++) {
        const int c = h * HDIM + 8 * eb + 2 * tig;
        *(float2*)&y[r0 * EMBD + c] = make_float2(acc[eb][0] * inv0, acc[eb][1] * inv0);
        *(float2*)&y[r1 * EMBD + c] = make_float2(acc[eb][2] * inv1, acc[eb][3] * inv1);
    }
}

// ---------------------------------------------------------------------------
extern "C" void kernel_launch(void* const* d_in, const int* in_sizes, int n_in,
                              void* d_out, int out_size) {
    const float* x      = (const float*)d_in[0];
    const float* W_attn = (const float*)d_in[1];
    const float* b_attn = (const float*)d_in[2];
    const float* W_proj = (const float*)d_in[3];
    const float* b_proj = (const float*)d_in[4];
    float* out = (float*)d_out;

    float* qkv;
    float* y;
    cudaGetSymbolAddress((void**)&qkv, g_qkv);
    cudaGetSymbolAddress((void**)&y, g_y);

    const int M = BATCH * SEQ;  // 8192

    cudaFuncSetAttribute(gemm_tf32, cudaFuncAttributeMaxDynamicSharedMemorySize, SMEM_BYTES);

    // 1) QKV projection
    {
        dim3 grid(QKV_C / 128, M / 128);
        gemm_tf32<<<grid, 256, SMEM_BYTES>>>(x, W_attn, b_attn, qkv, M, QKV_C, EMBD);
    }

    // 2) Causal flash attention (MMA)
    {
        dim3 grid(SEQ / 128, NHEAD, BATCH);
        flash_attn_mma<<<grid, 256>>>(qkv, y);
    }

    // 3) Output projection
    {
        dim3 grid(EMBD / 128, M / 128);
        gemm_tf32<<<grid, 256, SMEM_BYTES>>>(y, W_proj, b_proj, out, M, EMBD, EMBD);
    }
}